// round 16
// baseline (speedup 1.0000x reference)
#include <cuda_runtime.h>
#include <cuda_fp16.h>
#include <cstdint>
#include <math.h>

#define L 256
#define D 128
#define H 4
#define DH 32
#define NROW (L * L)
#define LOG2E 1.4426950408889634f

// ---------------- scratch (device globals; no allocations allowed) ----------
__device__ unsigned int g_xp16[NROW * D / 2];  // LN(x), fp16 A-frag (m16n8k16)
__device__ float g_q[NROW * D];       // q row-major (scaled by DH^-0.5*log2e)
__device__ float g_k[NROW * D];
__device__ float g_v[NROW * D];
__device__ unsigned int g_qp16[NROW * D / 2]; // per-(i,h) fp16 A-frag Q
__device__ unsigned int g_kp16[NROW * D / 2]; // per-(i,h) fp16 B-frag K^T
__device__ unsigned int g_vp16[NROW * D / 2]; // per-(i,h) fp16 B-frag V
__device__ float g_gate[NROW * D];    // sigmoid(x Wg + bg), row-major
__device__ float g_bias[H * NROW];    // biasT[h][j*L + k] (pre-multiplied by log2e)
__device__ unsigned int g_goutp16[NROW * D / 2]; // gate*attn_out, fp16 A-frag
__device__ unsigned int g_wp16[5 * 8192];        // 5 weights, fp16 B-frag

__device__ __forceinline__ float fast_ex2(float x) {
    float y;
    asm("ex2.approx.ftz.f32 %0, %1;" : "=f"(y) : "f"(x));
    return y;
}
__device__ __forceinline__ unsigned int pack_h2(float lo, float hi) {
    __half2 h = __floats2half2_rn(lo, hi);
    return *reinterpret_cast<unsigned int*>(&h);
}

// ---------------- fused LN + bias projection + fp16 A-fragment write --------
// Block = 16 rows (one m-tile), 512 threads, warp per row.
__global__ __launch_bounds__(512) void ln_fused_kernel(const float* __restrict__ pair,
                                                       const float* __restrict__ ln_w,
                                                       const float* __restrict__ ln_b,
                                                       const float* __restrict__ Wb) {
    __shared__ float s[16][132];
    int t = threadIdx.x;
    int lane = t & 31;
    int w = t >> 5;
    int n = blockIdx.x * 16 + w;

    const float4 xv = *(const float4*)&pair[(size_t)n * D + lane * 4];
    float sm  = xv.x + xv.y + xv.z + xv.w;
    float sm2 = xv.x * xv.x + xv.y * xv.y + xv.z * xv.z + xv.w * xv.w;
#pragma unroll
    for (int off = 16; off > 0; off >>= 1) {
        sm  += __shfl_xor_sync(0xffffffffu, sm,  off);
        sm2 += __shfl_xor_sync(0xffffffffu, sm2, off);
    }
    float mean = sm * (1.0f / 128.0f);
    float var  = sm2 * (1.0f / 128.0f) - mean * mean;
    float rstd = rsqrtf(var + 1e-5f);
    float4 w4 = *(const float4*)&ln_w[lane * 4];
    float4 b4 = *(const float4*)&ln_b[lane * 4];
    float o0 = (xv.x - mean) * rstd * w4.x + b4.x;
    float o1 = (xv.y - mean) * rstd * w4.y + b4.y;
    float o2 = (xv.z - mean) * rstd * w4.z + b4.z;
    float o3 = (xv.w - mean) * rstd * w4.w + b4.w;

    {
        float xs[4] = {o0, o1, o2, o3};
        float p0 = 0.f, p1 = 0.f, p2 = 0.f, p3 = 0.f;
#pragma unroll
        for (int q = 0; q < 4; q++) {
            float4 wb = *(const float4*)&Wb[(lane * 4 + q) * H];
            p0 += xs[q] * wb.x;
            p1 += xs[q] * wb.y;
            p2 += xs[q] * wb.z;
            p3 += xs[q] * wb.w;
        }
#pragma unroll
        for (int off = 16; off > 0; off >>= 1) {
            p0 += __shfl_xor_sync(0xffffffffu, p0, off);
            p1 += __shfl_xor_sync(0xffffffffu, p1, off);
            p2 += __shfl_xor_sync(0xffffffffu, p2, off);
            p3 += __shfl_xor_sync(0xffffffffu, p3, off);
        }
        if (lane == 0) {
            g_bias[0 * NROW + n] = p0 * LOG2E;
            g_bias[1 * NROW + n] = p1 * LOG2E;
            g_bias[2 * NROW + n] = p2 * LOG2E;
            g_bias[3 * NROW + n] = p3 * LOG2E;
        }
    }

    s[w][lane * 4 + 0] = o0;
    s[w][lane * 4 + 1] = o1;
    s[w][lane * 4 + 2] = o2;
    s[w][lane * 4 + 3] = o3;
    __syncthreads();

    // fp16 A-frag write (m16n8k16 map, mt=0 within block): 1024 u32 per tile
#pragma unroll
    for (int it = 0; it < 2; it++) {
        int idx = t + it * 512;
        int ks   = idx >> 7;
        int lane2 = (idx >> 2) & 31;
        int reg  = idx & 3;
        int g2 = lane2 >> 2, t2 = lane2 & 3;
        int row = (reg & 1) * 8 + g2;
        int d   = ks * 16 + ((reg >> 1) & 1) * 8 + 2 * t2;
        g_xp16[(size_t)blockIdx.x * 1024 + idx] = pack_h2(s[row][d], s[row][d + 1]);
    }
}

// ---------------- W permute -> fp16 B-frag ----------------------------------
// dst[ks8][nt16][lane*2+reg] = {W[k][n], W[k+1][n]}, k = ks*16+reg*8+2t, n = nt*8+g
__global__ __launch_bounds__(256) void permute_w_kernel(const float* __restrict__ Wq,
                                                        const float* __restrict__ Wk,
                                                        const float* __restrict__ Wv,
                                                        const float* __restrict__ Wg,
                                                        const float* __restrict__ Wo) {
    const float* srcs[5] = {Wq, Wk, Wv, Wg, Wo};
    const float* W = srcs[blockIdx.x];
    unsigned int* dst = g_wp16 + blockIdx.x * 8192;
    for (int i = threadIdx.x; i < 8192; i += 256) {
        int ks   = i >> 10;
        int nt   = (i >> 6) & 15;
        int lane = (i >> 1) & 31;
        int reg  = i & 1;
        int g2 = lane >> 2, t2 = lane & 3;
        int k = ks * 16 + reg * 8 + 2 * t2;
        int n = nt * 8 + g2;
        dst[i] = pack_h2(W[k * 128 + n], W[(k + 1) * 128 + n]);
    }
}

// ---------------- fp16 GEMM: [65536,128] @ [128,128] ------------------------
// Block tile 128x128, full K staged once (64 KB smem, single sync).
// wsel/blockIdx.y: 0=Q(scale), 1=K, 2=V, 3=gate(sigmoid) row-major fp32 out.
__global__ __launch_bounds__(256) void proj_gemm_kernel(const float* __restrict__ bg) {
    extern __shared__ unsigned int shp[];
    unsigned int* As = shp;          // 8192: [mt8][ks8][128]
    unsigned int* Bs = shp + 8192;   // 8192: [ks8][nt16][64]

    int t = threadIdx.x;
    int lane = t & 31;
    int warp = t >> 5;
    int warp_m = warp >> 1;
    int warp_n = warp & 1;
    int wsel = blockIdx.y;
    size_t mtb = (size_t)blockIdx.x * 8;
    const unsigned int* wp = g_wp16 + (size_t)wsel * 8192;

#pragma unroll
    for (int it = 0; it < 8; it++) {
        int f4 = t + it * 256;
        *(uint4*)&As[f4 * 4] = *(const uint4*)&g_xp16[(mtb * 1024) + f4 * 4];
    }
#pragma unroll
    for (int it = 0; it < 8; it++) {
        int f4 = t + it * 256;
        *(uint4*)&Bs[f4 * 4] = *(const uint4*)&wp[f4 * 4];
    }

    float acc[2][8][4];
#pragma unroll
    for (int wm = 0; wm < 2; wm++)
#pragma unroll
        for (int nt = 0; nt < 8; nt++)
#pragma unroll
            for (int r = 0; r < 4; r++) acc[wm][nt][r] = 0.0f;

    __syncthreads();

#pragma unroll
    for (int ks = 0; ks < 8; ks++) {
        uint4 afr[2];
        afr[0] = *(const uint4*)&As[(warp_m * 2 + 0) * 1024 + ks * 128 + lane * 4];
        afr[1] = *(const uint4*)&As[(warp_m * 2 + 1) * 1024 + ks * 128 + lane * 4];
        uint2 bfr[8];
#pragma unroll
        for (int nt = 0; nt < 8; nt++)
            bfr[nt] = *(const uint2*)&Bs[ks * 1024 + (warp_n * 8 + nt) * 64 + lane * 2];
#pragma unroll
        for (int wm = 0; wm < 2; wm++)
#pragma unroll
            for (int nt = 0; nt < 8; nt++) {
                asm volatile(
                    "mma.sync.aligned.m16n8k16.row.col.f32.f16.f16.f32 "
                    "{%0,%1,%2,%3}, {%4,%5,%6,%7}, {%8,%9}, {%0,%1,%2,%3};"
                    : "+f"(acc[wm][nt][0]), "+f"(acc[wm][nt][1]),
                      "+f"(acc[wm][nt][2]), "+f"(acc[wm][nt][3])
                    : "r"(afr[wm].x), "r"(afr[wm].y), "r"(afr[wm].z), "r"(afr[wm].w),
                      "r"(bfr[nt].x), "r"(bfr[nt].y));
            }
    }

    const float qscale = 0.17677669529663687f * LOG2E;
    float* out = (wsel == 0) ? g_q : (wsel == 1) ? g_k : (wsel == 2) ? g_v : g_gate;
    int g   = lane >> 2;
    int tid = lane & 3;
    int m0 = blockIdx.x * 128;
#pragma unroll
    for (int wm = 0; wm < 2; wm++) {
        int row0 = m0 + warp_m * 32 + wm * 16 + g;
#pragma unroll
        for (int nt = 0; nt < 8; nt++) {
            int col = warp_n * 64 + nt * 8 + tid * 2;
            float b0 = 0.f, b1 = 0.f;
            if (wsel == 3) { b0 = bg[col]; b1 = bg[col + 1]; }
            float v[4];
#pragma unroll
            for (int r = 0; r < 4; r++) {
                float a = acc[wm][nt][r];
                if (wsel == 0)      a *= qscale;
                else if (wsel == 3) a = 1.0f / (1.0f + __expf(-(a + ((r & 1) ? b1 : b0))));
                v[r] = a;
            }
            *(float2*)&out[(size_t)row0 * 128 + col]       = make_float2(v[0], v[1]);
            *(float2*)&out[(size_t)(row0 + 8) * 128 + col] = make_float2(v[2], v[3]);
        }
    }
}

// ---------------- attention operand permute (fp16 fragments) ----------------
__global__ __launch_bounds__(256) void attn_permute_kernel() {
    __shared__ float s[256][33];
    int t = threadIdx.x;
    int i = blockIdx.x;
    int h = blockIdx.y;
    size_t src_off = ((size_t)i * 256) * 128 + h * 32;
    size_t base = ((size_t)(i * 4 + h)) * 4096;

    const float* sq = g_q + src_off;
    const float* sk = g_k + src_off;
    const float* sv = g_v + src_off;

#pragma unroll 1
    for (int phase = 0; phase < 3; phase++) {
        const float* src = (phase == 0) ? sq : (phase == 1) ? sk : sv;
        unsigned int* dst = (phase == 0) ? (g_qp16 + base)
                           : (phase == 1) ? (g_kp16 + base) : (g_vp16 + base);
#pragma unroll
        for (int it = 0; it < 8; it++) {
            int f4 = t + it * 256;
            int r  = f4 >> 3;
            int c4 = f4 & 7;
            float4 v = *(const float4*)&src[(size_t)r * 128 + c4 * 4];
            s[r][c4 * 4 + 0] = v.x;
            s[r][c4 * 4 + 1] = v.y;
            s[r][c4 * 4 + 2] = v.z;
            s[r][c4 * 4 + 3] = v.w;
        }
        __syncthreads();
        if (phase == 0) {
#pragma unroll
            for (int it = 0; it < 16; it++) {
                int idx = it * 256 + t;
                int mt   = idx >> 8;
                int ks   = (idx >> 7) & 1;
                int lane = (idx >> 2) & 31;
                int reg  = idx & 3;
                int g2 = lane >> 2, t2 = lane & 3;
                int row = mt * 16 + (reg & 1) * 8 + g2;
                int d   = ks * 16 + ((reg >> 1) & 1) * 8 + 2 * t2;
                dst[idx] = pack_h2(s[row][d], s[row][d + 1]);
            }
        } else if (phase == 1) {
#pragma unroll
            for (int it = 0; it < 16; it++) {
                int idx = it * 256 + t;
                int ntg  = idx >> 7;
                int ks   = (idx >> 6) & 1;
                int lane = (idx >> 1) & 31;
                int reg  = idx & 1;
                int g2 = lane >> 2, t2 = lane & 3;
                int key = ntg * 8 + g2;
                int d   = ks * 16 + reg * 8 + 2 * t2;
                dst[idx] = pack_h2(s[key][d], s[key][d + 1]);
            }
        } else {
#pragma unroll
            for (int it = 0; it < 16; it++) {
                int idx = it * 256 + t;
                int kc   = idx >> 8;
                int ntd  = (idx >> 6) & 3;
                int lane = (idx >> 1) & 31;
                int reg  = idx & 1;
                int g2 = lane >> 2, t2 = lane & 3;
                int key = kc * 16 + reg * 8 + 2 * t2;
                int d   = ntd * 8 + g2;
                dst[idx] = pack_h2(s[key][d], s[key + 1][d]);
            }
        }
        __syncthreads();
    }
}

// ---------------- fp16 tensor-core attention (K/V staged in shared) ---------
__global__ __launch_bounds__(256) void attn_mma_kernel() {
    extern __shared__ unsigned int shu[];
    unsigned int* Ks16 = shu;           // 4096
    unsigned int* Vs16 = shu + 4096;    // 4096
    unsigned int* Pall = shu + 8192;    // 8*256

    int t = threadIdx.x;
    int lane = t & 31;
    int warp = t >> 5;
    int g  = lane >> 2;
    int tq = lane & 3;
    int i  = blockIdx.x;
    int jt = blockIdx.y;
    int h  = blockIdx.z;

    size_t base = ((size_t)(i * 4 + h)) * 4096;
    const unsigned int* qp = g_qp16 + base;
    const unsigned int* kp = g_kp16 + base;
    const unsigned int* vp = g_vp16 + base;

#pragma unroll
    for (int it = 0; it < 4; it++) {
        int f4 = t + it * 256;
        *(uint4*)&Ks16[f4 * 4] = *(const uint4*)&kp[f4 * 4];
    }
#pragma unroll
    for (int it = 0; it < 4; it++) {
        int f4 = t + it * 256;
        *(uint4*)&Vs16[f4 * 4] = *(const uint4*)&vp[f4 * 4];
    }

    int mt_global = jt * 8 + warp;
    int j0 = mt_global * 16;

    uint4 qf[2];
#pragma unroll
    for (int ks = 0; ks < 2; ks++)
        qf[ks] = *(const uint4*)&qp[mt_global * 256 + ks * 128 + lane * 4];

    const float* brow0 = g_bias + (size_t)h * NROW + (size_t)(j0 + g) * 256;
    const float* brow1 = brow0 + 8 * 256;

    float lsum0 = 0.f, lsum1 = 0.f;
    float oacc[4][4];
#pragma unroll
    for (int nt = 0; nt < 4; nt++)
#pragma unroll
        for (int r = 0; r < 4; r++) oacc[nt][r] = 0.f;

    unsigned int* pb = &Pall[warp * 256];

    __syncthreads();

    for (int c = 0; c < 8; c++) {
#pragma unroll
        for (int nt = 0; nt < 4; nt++) {
            float sacc[4] = {0.f, 0.f, 0.f, 0.f};
#pragma unroll
            for (int ks = 0; ks < 2; ks++) {
                uint2 kf = *(const uint2*)&Ks16[((c * 4 + nt) * 2 + ks) * 64 + lane * 2];
                asm volatile(
                    "mma.sync.aligned.m16n8k16.row.col.f32.f16.f16.f32 "
                    "{%0,%1,%2,%3}, {%4,%5,%6,%7}, {%8,%9}, {%0,%1,%2,%3};"
                    : "+f"(sacc[0]), "+f"(sacc[1]), "+f"(sacc[2]), "+f"(sacc[3])
                    : "r"(qf[ks].x), "r"(qf[ks].y), "r"(qf[ks].z), "r"(qf[ks].w),
                      "r"(kf.x), "r"(kf.y));
            }
            int keyc = c * 32 + nt * 8 + tq * 2;
            float2 b0 = *(const float2*)&brow0[keyc];
            float2 b1 = *(const float2*)&brow1[keyc];
            float p0 = fast_ex2(sacc[0] + b0.x);
            float p1 = fast_ex2(sacc[1] + b0.y);
            float p2 = fast_ex2(sacc[2] + b1.x);
            float p3 = fast_ex2(sacc[3] + b1.y);
            lsum0 += p0 + p1;
            lsum1 += p2 + p3;
            pb[nt * 64 + g * 4 + tq]        = pack_h2(p0, p1);
            pb[nt * 64 + (g + 8) * 4 + tq]  = pack_h2(p2, p3);
        }
        __syncwarp();
#pragma unroll
        for (int cc = 0; cc < 2; cc++) {
            unsigned int pa0 = pb[(2 * cc) * 64 + g * 4 + tq];
            unsigned int pa1 = pb[(2 * cc) * 64 + (g + 8) * 4 + tq];
            unsigned int pa2 = pb[(2 * cc + 1) * 64 + g * 4 + tq];
            unsigned int pa3 = pb[(2 * cc + 1) * 64 + (g + 8) * 4 + tq];
#pragma unroll
            for (int ntd = 0; ntd < 4; ntd++) {
                uint2 vf = *(const uint2*)&Vs16[((c * 2 + cc) * 4 + ntd) * 64 + lane * 2];
                asm volatile(
                    "mma.sync.aligned.m16n8k16.row.col.f32.f16.f16.f32 "
                    "{%0,%1,%2,%3}, {%4,%5,%6,%7}, {%8,%9}, {%0,%1,%2,%3};"
                    : "+f"(oacc[ntd][0]), "+f"(oacc[ntd][1]),
                      "+f"(oacc[ntd][2]), "+f"(oacc[ntd][3])
                    : "r"(pa0), "r"(pa1), "r"(pa2), "r"(pa3),
                      "r"(vf.x), "r"(vf.y));
            }
        }
        __syncwarp();
    }

    lsum0 += __shfl_xor_sync(0xffffffffu, lsum0, 1);
    lsum0 += __shfl_xor_sync(0xffffffffu, lsum0, 2);
    lsum1 += __shfl_xor_sync(0xffffffffu, lsum1, 1);
    lsum1 += __shfl_xor_sync(0xffffffffu, lsum1, 2);
    float inv0 = 1.0f / lsum0;
    float inv1 = 1.0f / lsum1;

    // ---- gated output -> fp16 A-frag (d_global = h*32 + ntd*8 + 2tq) -------
    size_t row0 = (size_t)(i * 256 + j0 + g) * 128 + h * 32;
    size_t row1 = row0 + 8 * 128;
#pragma unroll
    for (int ntd = 0; ntd < 4; ntd++) {
        int col = ntd * 8 + tq * 2;
        float2 g0 = *(const float2*)&g_gate[row0 + col];
        float2 g1 = *(const float2*)&g_gate[row1 + col];
        float v0 = oacc[ntd][0] * inv0 * g0.x;
        float v1 = oacc[ntd][1] * inv0 * g0.y;
        float v2 = oacc[ntd][2] * inv1 * g1.x;
        float v3 = oacc[ntd][3] * inv1 * g1.y;
        int ks_local = ntd >> 1;
        int regb = 2 * (ntd & 1);
        pb[ks_local * 128 + lane * 4 + regb]     = pack_h2(v0, v1);  // rows g
        pb[ks_local * 128 + lane * 4 + regb + 1] = pack_h2(v2, v3);  // rows g+8
    }
    __syncwarp();
    size_t tile = (size_t)(i * 16 + mt_global);
    unsigned int* dst = g_goutp16 + tile * 1024 + h * 256;
#pragma unroll
    for (int q = 0; q < 2; q++) {
        *(uint4*)&dst[(q * 32 + lane) * 4] = *(const uint4*)&pb[(q * 32 + lane) * 4];
    }
}

// ---------------- final output GEMM (fp16) ----------------------------------
__global__ __launch_bounds__(256) void gemm_out_kernel(float* __restrict__ out,
                                                       const float* __restrict__ bias) {
    extern __shared__ unsigned int shp[];
    unsigned int* As = shp;
    unsigned int* Bs = shp + 8192;

    int t = threadIdx.x;
    int lane = t & 31;
    int warp = t >> 5;
    int warp_m = warp >> 1;
    int warp_n = warp & 1;
    size_t mtb = (size_t)blockIdx.x * 8;
    const unsigned int* wp = g_wp16 + (size_t)4 * 8192;

#pragma unroll
    for (int it = 0; it < 8; it++) {
        int f4 = t + it * 256;
        *(uint4*)&As[f4 * 4] = *(const uint4*)&g_goutp16[(mtb * 1024) + f4 * 4];
    }
#pragma unroll
    for (int it = 0; it < 8; it++) {
        int f4 = t + it * 256;
        *(uint4*)&Bs[f4 * 4] = *(const uint4*)&wp[f4 * 4];
    }

    float acc[2][8][4];
#pragma unroll
    for (int wm = 0; wm < 2; wm++)
#pragma unroll
        for (int nt = 0; nt < 8; nt++)
#pragma unroll
            for (int r = 0; r < 4; r++) acc[wm][nt][r] = 0.0f;

    __syncthreads();

#pragma unroll
    for (int ks = 0; ks < 8; ks++) {
        uint4 afr[2];
        afr[0] = *(const uint4*)&As[(warp_m * 2 + 0) * 1024 + ks * 128 + lane * 4];
        afr[1] = *(const uint4*)&As[(warp_m * 2 + 1) * 1024 + ks * 128 + lane * 4];
        uint2 bfr[8];
#pragma unroll
        for (int nt = 0; nt < 8; nt++)
            bfr[nt] = *(const uint2*)&Bs[ks * 1024 + (warp_n * 8 + nt) * 64 + lane * 2];
#pragma unroll
        for (int wm = 0; wm < 2; wm++)
#pragma unroll
            for (int nt = 0; nt < 8; nt++) {
                asm volatile(
                    "mma.sync.aligned.m16n8k16.row.col.f32.f16.f16.f32 "
                    "{%0,%1,%2,%3}, {%4,%5,%6,%7}, {%8,%9}, {%0,%1,%2,%3};"
                    : "+f"(acc[wm][nt][0]), "+f"(acc[wm][nt][1]),
                      "+f"(acc[wm][nt][2]), "+f"(acc[wm][nt][3])
                    : "r"(afr[wm].x), "r"(afr[wm].y), "r"(afr[wm].z), "r"(afr[wm].w),
                      "r"(bfr[nt].x), "r"(bfr[nt].y));
            }
    }

    int g   = lane >> 2;
    int tid = lane & 3;
    int m0 = blockIdx.x * 128;
#pragma unroll
    for (int wm = 0; wm < 2; wm++) {
        int row0 = m0 + warp_m * 32 + wm * 16 + g;
#pragma unroll
        for (int nt = 0; nt < 8; nt++) {
            int col = warp_n * 64 + nt * 8 + tid * 2;
            float b0 = bias[col], b1 = bias[col + 1];
            *(float2*)&out[(size_t)row0 * 128 + col] =
                make_float2(acc[wm][nt][0] + b0, acc[wm][nt][1] + b1);
            *(float2*)&out[(size_t)(row0 + 8) * 128 + col] =
                make_float2(acc[wm][nt][2] + b0, acc[wm][nt][3] + b1);
        }
    }
}

// ---------------- launch ----------------------------------------------------
extern "C" void kernel_launch(void* const* d_in, const int* in_sizes, int n_in,
                              void* d_out, int out_size) {
    const float* pair = (const float*)d_in[0];
    const float* ln_w = (const float*)d_in[1];
    const float* ln_b = (const float*)d_in[2];
    const float* Wq   = (const float*)d_in[3];
    const float* Wk   = (const float*)d_in[4];
    const float* Wv   = (const float*)d_in[5];
    const float* Wb   = (const float*)d_in[6];
    const float* Wg   = (const float*)d_in[7];
    const float* bg   = (const float*)d_in[8];
    const float* Wo   = (const float*)d_in[9];
    const float* bo   = (const float*)d_in[10];
    float* out = (float*)d_out;

    cudaFuncSetAttribute(proj_gemm_kernel, cudaFuncAttributeMaxDynamicSharedMemorySize,
                         16384 * (int)sizeof(unsigned int));
    cudaFuncSetAttribute(gemm_out_kernel, cudaFuncAttributeMaxDynamicSharedMemorySize,
                         16384 * (int)sizeof(unsigned int));
    cudaFuncSetAttribute(attn_mma_kernel, cudaFuncAttributeMaxDynamicSharedMemorySize,
                         (4096 + 4096 + 8 * 256) * (int)sizeof(unsigned int));

    ln_fused_kernel<<<NROW / 16, 512>>>(pair, ln_w, ln_b, Wb);
    permute_w_kernel<<<5, 256>>>(Wq, Wk, Wv, Wg, Wo);

    proj_gemm_kernel<<<dim3(NROW / 128, 4), 256, 16384 * sizeof(unsigned int)>>>(bg);

    attn_permute_kernel<<<dim3(L, H), 256>>>();
    attn_mma_kernel<<<dim3(L, 2, H), 256,
                      (4096 + 4096 + 8 * 256) * sizeof(unsigned int)>>>();

    gemm_out_kernel<<<NROW / 128, 256, 16384 * sizeof(unsigned int)>>>(out, bo);
}

// round 17
// speedup vs baseline: 1.4045x; 1.4045x over previous
#include <cuda_runtime.h>
#include <cuda_fp16.h>
#include <cstdint>
#include <math.h>

#define L 256
#define D 128
#define H 4
#define DH 32
#define NROW (L * L)
#define LOG2E 1.4426950408889634f

// ---------------- scratch (device globals; no allocations allowed) ----------
__device__ unsigned int g_xp16[NROW * D / 2];  // LN(x), fp16 A-frag (m16n8k16)
__device__ float g_q[NROW * D];       // q row-major (scaled by DH^-0.5*log2e)
__device__ float g_k[NROW * D];
__device__ float g_v[NROW * D];
__device__ unsigned int g_qp16[NROW * D / 2]; // per-(i,h) fp16 A-frag Q
__device__ unsigned int g_kp16[NROW * D / 2]; // per-(i,h) fp16 B-frag K^T
__device__ unsigned int g_vp16[NROW * D / 2]; // per-(i,h) fp16 B-frag V
__device__ float g_gate[NROW * D];    // sigmoid(x Wg + bg), row-major
__device__ float g_bias[H * NROW];    // biasT[h][j*L + k] (pre-multiplied by log2e)
__device__ unsigned int g_goutp16[NROW * D / 2]; // gate*attn_out, fp16 A-frag
__device__ unsigned int g_wp16[5 * 8192];        // 5 weights, fp16 B-frag

__device__ __forceinline__ float fast_ex2(float x) {
    float y;
    asm("ex2.approx.ftz.f32 %0, %1;" : "=f"(y) : "f"(x));
    return y;
}
__device__ __forceinline__ unsigned int pack_h2(float lo, float hi) {
    __half2 h = __floats2half2_rn(lo, hi);
    return *reinterpret_cast<unsigned int*>(&h);
}

// ---------------- fused LN + bias projection + fp16 A-fragment write --------
__global__ __launch_bounds__(512) void ln_fused_kernel(const float* __restrict__ pair,
                                                       const float* __restrict__ ln_w,
                                                       const float* __restrict__ ln_b,
                                                       const float* __restrict__ Wb) {
    __shared__ float s[16][132];
    int t = threadIdx.x;
    int lane = t & 31;
    int w = t >> 5;
    int n = blockIdx.x * 16 + w;

    const float4 xv = *(const float4*)&pair[(size_t)n * D + lane * 4];
    float sm  = xv.x + xv.y + xv.z + xv.w;
    float sm2 = xv.x * xv.x + xv.y * xv.y + xv.z * xv.z + xv.w * xv.w;
#pragma unroll
    for (int off = 16; off > 0; off >>= 1) {
        sm  += __shfl_xor_sync(0xffffffffu, sm,  off);
        sm2 += __shfl_xor_sync(0xffffffffu, sm2, off);
    }
    float mean = sm * (1.0f / 128.0f);
    float var  = sm2 * (1.0f / 128.0f) - mean * mean;
    float rstd = rsqrtf(var + 1e-5f);
    float4 w4 = *(const float4*)&ln_w[lane * 4];
    float4 b4 = *(const float4*)&ln_b[lane * 4];
    float o0 = (xv.x - mean) * rstd * w4.x + b4.x;
    float o1 = (xv.y - mean) * rstd * w4.y + b4.y;
    float o2 = (xv.z - mean) * rstd * w4.z + b4.z;
    float o3 = (xv.w - mean) * rstd * w4.w + b4.w;

    {
        float xs[4] = {o0, o1, o2, o3};
        float p0 = 0.f, p1 = 0.f, p2 = 0.f, p3 = 0.f;
#pragma unroll
        for (int q = 0; q < 4; q++) {
            float4 wb = *(const float4*)&Wb[(lane * 4 + q) * H];
            p0 += xs[q] * wb.x;
            p1 += xs[q] * wb.y;
            p2 += xs[q] * wb.z;
            p3 += xs[q] * wb.w;
        }
#pragma unroll
        for (int off = 16; off > 0; off >>= 1) {
            p0 += __shfl_xor_sync(0xffffffffu, p0, off);
            p1 += __shfl_xor_sync(0xffffffffu, p1, off);
            p2 += __shfl_xor_sync(0xffffffffu, p2, off);
            p3 += __shfl_xor_sync(0xffffffffu, p3, off);
        }
        if (lane == 0) {
            g_bias[0 * NROW + n] = p0 * LOG2E;
            g_bias[1 * NROW + n] = p1 * LOG2E;
            g_bias[2 * NROW + n] = p2 * LOG2E;
            g_bias[3 * NROW + n] = p3 * LOG2E;
        }
    }

    s[w][lane * 4 + 0] = o0;
    s[w][lane * 4 + 1] = o1;
    s[w][lane * 4 + 2] = o2;
    s[w][lane * 4 + 3] = o3;
    __syncthreads();

    // fp16 A-frag write (m16n8k16 map): 1024 u32 per 16-row tile
#pragma unroll
    for (int it = 0; it < 2; it++) {
        int idx = t + it * 512;
        int ks   = idx >> 7;
        int lane2 = (idx >> 2) & 31;
        int reg  = idx & 3;
        int g2 = lane2 >> 2, t2 = lane2 & 3;
        int row = (reg & 1) * 8 + g2;
        int d   = ks * 16 + ((reg >> 1) & 1) * 8 + 2 * t2;
        g_xp16[(size_t)blockIdx.x * 1024 + idx] = pack_h2(s[row][d], s[row][d + 1]);
    }
}

// ---------------- W permute -> fp16 B-frag ----------------------------------
__global__ __launch_bounds__(256) void permute_w_kernel(const float* __restrict__ Wq,
                                                        const float* __restrict__ Wk,
                                                        const float* __restrict__ Wv,
                                                        const float* __restrict__ Wg,
                                                        const float* __restrict__ Wo) {
    const float* srcs[5] = {Wq, Wk, Wv, Wg, Wo};
    const float* W = srcs[blockIdx.x];
    unsigned int* dst = g_wp16 + blockIdx.x * 8192;
    for (int i = threadIdx.x; i < 8192; i += 256) {
        int ks   = i >> 10;
        int nt   = (i >> 6) & 15;
        int lane = (i >> 1) & 31;
        int reg  = i & 1;
        int g2 = lane >> 2, t2 = lane & 3;
        int k = ks * 16 + reg * 8 + 2 * t2;
        int n = nt * 8 + g2;
        dst[i] = pack_h2(W[k * 128 + n], W[(k + 1) * 128 + n]);
    }
}

// ---------------- fp16 GEMM, k-chunked (validated pipeline shape) -----------
// Block tile 128x128; K split into 2 chunks of 4 ks-steps (32 KB static smem).
// wsel/blockIdx.y: 0=Q(scale), 1=K, 2=V, 3=gate(sigmoid) row-major fp32 out.
__global__ __launch_bounds__(256) void proj_gemm_kernel(const float* __restrict__ bg) {
    __shared__ unsigned int As[8][512];  // [mt][ksl4 * 128]
    __shared__ unsigned int Bs[4096];    // [ksl4][nt16][64]

    int t = threadIdx.x;
    int lane = t & 31;
    int warp = t >> 5;
    int warp_m = warp >> 1;
    int warp_n = warp & 1;
    int wsel = blockIdx.y;
    size_t mtb = (size_t)blockIdx.x * 8;
    const unsigned int* wp = g_wp16 + (size_t)wsel * 8192;

    float acc[2][8][4];
#pragma unroll
    for (int wm = 0; wm < 2; wm++)
#pragma unroll
        for (int nt = 0; nt < 8; nt++)
#pragma unroll
            for (int r = 0; r < 4; r++) acc[wm][nt][r] = 0.0f;

    for (int c = 0; c < 2; c++) {
        // A chunk: per tile, 512 contiguous u32 at offset c*512 (128 uint4)
#pragma unroll
        for (int it = 0; it < 4; it++) {
            int f4 = t + it * 256;       // 0..1023
            int mt  = f4 >> 7;
            int off = f4 & 127;
            *(uint4*)&As[mt][off * 4] =
                *(const uint4*)&g_xp16[(mtb + mt) * 1024 + c * 512 + off * 4];
        }
        // B chunk: 4096 contiguous u32 at offset c*4096 (1024 uint4)
#pragma unroll
        for (int it = 0; it < 4; it++) {
            int f4 = t + it * 256;
            *(uint4*)&Bs[f4 * 4] = *(const uint4*)&wp[c * 4096 + f4 * 4];
        }
        __syncthreads();

#pragma unroll
        for (int ksl = 0; ksl < 4; ksl++) {
            uint4 afr[2];
            afr[0] = *(const uint4*)&As[warp_m * 2 + 0][ksl * 128 + lane * 4];
            afr[1] = *(const uint4*)&As[warp_m * 2 + 1][ksl * 128 + lane * 4];
            uint2 bfr[8];
#pragma unroll
            for (int nt = 0; nt < 8; nt++)
                bfr[nt] = *(const uint2*)&Bs[ksl * 1024 + (warp_n * 8 + nt) * 64 + lane * 2];
#pragma unroll
            for (int wm = 0; wm < 2; wm++)
#pragma unroll
                for (int nt = 0; nt < 8; nt++) {
                    asm volatile(
                        "mma.sync.aligned.m16n8k16.row.col.f32.f16.f16.f32 "
                        "{%0,%1,%2,%3}, {%4,%5,%6,%7}, {%8,%9}, {%0,%1,%2,%3};"
                        : "+f"(acc[wm][nt][0]), "+f"(acc[wm][nt][1]),
                          "+f"(acc[wm][nt][2]), "+f"(acc[wm][nt][3])
                        : "r"(afr[wm].x), "r"(afr[wm].y), "r"(afr[wm].z), "r"(afr[wm].w),
                          "r"(bfr[nt].x), "r"(bfr[nt].y));
                }
        }
        __syncthreads();
    }

    const float qscale = 0.17677669529663687f * LOG2E;
    float* out = (wsel == 0) ? g_q : (wsel == 1) ? g_k : (wsel == 2) ? g_v : g_gate;
    int g   = lane >> 2;
    int tid = lane & 3;
    int m0 = blockIdx.x * 128;
#pragma unroll
    for (int wm = 0; wm < 2; wm++) {
        int row0 = m0 + warp_m * 32 + wm * 16 + g;
#pragma unroll
        for (int nt = 0; nt < 8; nt++) {
            int col = warp_n * 64 + nt * 8 + tid * 2;
            float b0 = 0.f, b1 = 0.f;
            if (wsel == 3) { b0 = bg[col]; b1 = bg[col + 1]; }
            float v[4];
#pragma unroll
            for (int r = 0; r < 4; r++) {
                float a = acc[wm][nt][r];
                if (wsel == 0)      a *= qscale;
                else if (wsel == 3) a = 1.0f / (1.0f + __expf(-(a + ((r & 1) ? b1 : b0))));
                v[r] = a;
            }
            *(float2*)&out[(size_t)row0 * 128 + col]       = make_float2(v[0], v[1]);
            *(float2*)&out[(size_t)(row0 + 8) * 128 + col] = make_float2(v[2], v[3]);
        }
    }
}

// ---------------- attention operand permute (fp16 fragments) ----------------
__global__ __launch_bounds__(256) void attn_permute_kernel() {
    __shared__ float s[256][33];
    int t = threadIdx.x;
    int i = blockIdx.x;
    int h = blockIdx.y;
    size_t src_off = ((size_t)i * 256) * 128 + h * 32;
    size_t base = ((size_t)(i * 4 + h)) * 4096;

    const float* sq = g_q + src_off;
    const float* sk = g_k + src_off;
    const float* sv = g_v + src_off;

#pragma unroll 1
    for (int phase = 0; phase < 3; phase++) {
        const float* src = (phase == 0) ? sq : (phase == 1) ? sk : sv;
        unsigned int* dst = (phase == 0) ? (g_qp16 + base)
                           : (phase == 1) ? (g_kp16 + base) : (g_vp16 + base);
#pragma unroll
        for (int it = 0; it < 8; it++) {
            int f4 = t + it * 256;
            int r  = f4 >> 3;
            int c4 = f4 & 7;
            float4 v = *(const float4*)&src[(size_t)r * 128 + c4 * 4];
            s[r][c4 * 4 + 0] = v.x;
            s[r][c4 * 4 + 1] = v.y;
            s[r][c4 * 4 + 2] = v.z;
            s[r][c4 * 4 + 3] = v.w;
        }
        __syncthreads();
        if (phase == 0) {
#pragma unroll
            for (int it = 0; it < 16; it++) {
                int idx = it * 256 + t;
                int mt   = idx >> 8;
                int ks   = (idx >> 7) & 1;
                int lane = (idx >> 2) & 31;
                int reg  = idx & 3;
                int g2 = lane >> 2, t2 = lane & 3;
                int row = mt * 16 + (reg & 1) * 8 + g2;
                int d   = ks * 16 + ((reg >> 1) & 1) * 8 + 2 * t2;
                dst[idx] = pack_h2(s[row][d], s[row][d + 1]);
            }
        } else if (phase == 1) {
#pragma unroll
            for (int it = 0; it < 16; it++) {
                int idx = it * 256 + t;
                int ntg  = idx >> 7;
                int ks   = (idx >> 6) & 1;
                int lane = (idx >> 1) & 31;
                int reg  = idx & 1;
                int g2 = lane >> 2, t2 = lane & 3;
                int key = ntg * 8 + g2;
                int d   = ks * 16 + reg * 8 + 2 * t2;
                dst[idx] = pack_h2(s[key][d], s[key][d + 1]);
            }
        } else {
#pragma unroll
            for (int it = 0; it < 16; it++) {
                int idx = it * 256 + t;
                int kc   = idx >> 8;
                int ntd  = (idx >> 6) & 3;
                int lane = (idx >> 1) & 31;
                int reg  = idx & 1;
                int g2 = lane >> 2, t2 = lane & 3;
                int key = kc * 16 + reg * 8 + 2 * t2;
                int d   = ntd * 8 + g2;
                dst[idx] = pack_h2(s[key][d], s[key + 1][d]);
            }
        }
        __syncthreads();
    }
}

// ---------------- fp16 tensor-core attention (K/V staged in shared) ---------
__global__ __launch_bounds__(256) void attn_mma_kernel() {
    extern __shared__ unsigned int shu[];
    unsigned int* Ks16 = shu;           // 4096
    unsigned int* Vs16 = shu + 4096;    // 4096
    unsigned int* Pall = shu + 8192;    // 8*256

    int t = threadIdx.x;
    int lane = t & 31;
    int warp = t >> 5;
    int g  = lane >> 2;
    int tq = lane & 3;
    int i  = blockIdx.x;
    int jt = blockIdx.y;
    int h  = blockIdx.z;

    size_t base = ((size_t)(i * 4 + h)) * 4096;
    const unsigned int* qp = g_qp16 + base;
    const unsigned int* kp = g_kp16 + base;
    const unsigned int* vp = g_vp16 + base;

#pragma unroll
    for (int it = 0; it < 4; it++) {
        int f4 = t + it * 256;
        *(uint4*)&Ks16[f4 * 4] = *(const uint4*)&kp[f4 * 4];
    }
#pragma unroll
    for (int it = 0; it < 4; it++) {
        int f4 = t + it * 256;
        *(uint4*)&Vs16[f4 * 4] = *(const uint4*)&vp[f4 * 4];
    }

    int mt_global = jt * 8 + warp;
    int j0 = mt_global * 16;

    uint4 qf[2];
#pragma unroll
    for (int ks = 0; ks < 2; ks++)
        qf[ks] = *(const uint4*)&qp[mt_global * 256 + ks * 128 + lane * 4];

    const float* brow0 = g_bias + (size_t)h * NROW + (size_t)(j0 + g) * 256;
    const float* brow1 = brow0 + 8 * 256;

    float lsum0 = 0.f, lsum1 = 0.f;
    float oacc[4][4];
#pragma unroll
    for (int nt = 0; nt < 4; nt++)
#pragma unroll
        for (int r = 0; r < 4; r++) oacc[nt][r] = 0.f;

    unsigned int* pb = &Pall[warp * 256];

    __syncthreads();

    for (int c = 0; c < 8; c++) {
#pragma unroll
        for (int nt = 0; nt < 4; nt++) {
            float sacc[4] = {0.f, 0.f, 0.f, 0.f};
#pragma unroll
            for (int ks = 0; ks < 2; ks++) {
                uint2 kf = *(const uint2*)&Ks16[((c * 4 + nt) * 2 + ks) * 64 + lane * 2];
                asm volatile(
                    "mma.sync.aligned.m16n8k16.row.col.f32.f16.f16.f32 "
                    "{%0,%1,%2,%3}, {%4,%5,%6,%7}, {%8,%9}, {%0,%1,%2,%3};"
                    : "+f"(sacc[0]), "+f"(sacc[1]), "+f"(sacc[2]), "+f"(sacc[3])
                    : "r"(qf[ks].x), "r"(qf[ks].y), "r"(qf[ks].z), "r"(qf[ks].w),
                      "r"(kf.x), "r"(kf.y));
            }
            int keyc = c * 32 + nt * 8 + tq * 2;
            float2 b0 = *(const float2*)&brow0[keyc];
            float2 b1 = *(const float2*)&brow1[keyc];
            float p0 = fast_ex2(sacc[0] + b0.x);
            float p1 = fast_ex2(sacc[1] + b0.y);
            float p2 = fast_ex2(sacc[2] + b1.x);
            float p3 = fast_ex2(sacc[3] + b1.y);
            lsum0 += p0 + p1;
            lsum1 += p2 + p3;
            pb[nt * 64 + g * 4 + tq]        = pack_h2(p0, p1);
            pb[nt * 64 + (g + 8) * 4 + tq]  = pack_h2(p2, p3);
        }
        __syncwarp();
#pragma unroll
        for (int cc = 0; cc < 2; cc++) {
            unsigned int pa0 = pb[(2 * cc) * 64 + g * 4 + tq];
            unsigned int pa1 = pb[(2 * cc) * 64 + (g + 8) * 4 + tq];
            unsigned int pa2 = pb[(2 * cc + 1) * 64 + g * 4 + tq];
            unsigned int pa3 = pb[(2 * cc + 1) * 64 + (g + 8) * 4 + tq];
#pragma unroll
            for (int ntd = 0; ntd < 4; ntd++) {
                uint2 vf = *(const uint2*)&Vs16[((c * 2 + cc) * 4 + ntd) * 64 + lane * 2];
                asm volatile(
                    "mma.sync.aligned.m16n8k16.row.col.f32.f16.f16.f32 "
                    "{%0,%1,%2,%3}, {%4,%5,%6,%7}, {%8,%9}, {%0,%1,%2,%3};"
                    : "+f"(oacc[ntd][0]), "+f"(oacc[ntd][1]),
                      "+f"(oacc[ntd][2]), "+f"(oacc[ntd][3])
                    : "r"(pa0), "r"(pa1), "r"(pa2), "r"(pa3),
                      "r"(vf.x), "r"(vf.y));
            }
        }
        __syncwarp();
    }

    lsum0 += __shfl_xor_sync(0xffffffffu, lsum0, 1);
    lsum0 += __shfl_xor_sync(0xffffffffu, lsum0, 2);
    lsum1 += __shfl_xor_sync(0xffffffffu, lsum1, 1);
    lsum1 += __shfl_xor_sync(0xffffffffu, lsum1, 2);
    float inv0 = 1.0f / lsum0;
    float inv1 = 1.0f / lsum1;

    // ---- gated output -> fp16 A-frag (validated R16 epilogue) --------------
    size_t row0 = (size_t)(i * 256 + j0 + g) * 128 + h * 32;
    size_t row1 = row0 + 8 * 128;
#pragma unroll
    for (int ntd = 0; ntd < 4; ntd++) {
        int col = ntd * 8 + tq * 2;
        float2 g0 = *(const float2*)&g_gate[row0 + col];
        float2 g1 = *(const float2*)&g_gate[row1 + col];
        float v0 = oacc[ntd][0] * inv0 * g0.x;
        float v1 = oacc[ntd][1] * inv0 * g0.y;
        float v2 = oacc[ntd][2] * inv1 * g1.x;
        float v3 = oacc[ntd][3] * inv1 * g1.y;
        int ks_local = ntd >> 1;
        int regb = 2 * (ntd & 1);
        pb[ks_local * 128 + lane * 4 + regb]     = pack_h2(v0, v1);
        pb[ks_local * 128 + lane * 4 + regb + 1] = pack_h2(v2, v3);
    }
    __syncwarp();
    size_t tile = (size_t)(i * 16 + mt_global);
    unsigned int* dst = g_goutp16 + tile * 1024 + h * 256;
#pragma unroll
    for (int q = 0; q < 2; q++) {
        *(uint4*)&dst[(q * 32 + lane) * 4] = *(const uint4*)&pb[(q * 32 + lane) * 4];
    }
}

// ---------------- final output GEMM (fp16, k-chunked) -----------------------
__global__ __launch_bounds__(256) void gemm_out_kernel(float* __restrict__ out,
                                                       const float* __restrict__ bias) {
    __shared__ unsigned int As[8][512];
    __shared__ unsigned int Bs[4096];

    int t = threadIdx.x;
    int lane = t & 31;
    int warp = t >> 5;
    int warp_m = warp >> 1;
    int warp_n = warp & 1;
    size_t mtb = (size_t)blockIdx.x * 8;
    const unsigned int* wp = g_wp16 + (size_t)4 * 8192;

    float acc[2][8][4];
#pragma unroll
    for (int wm = 0; wm < 2; wm++)
#pragma unroll
        for (int nt = 0; nt < 8; nt++)
#pragma unroll
            for (int r = 0; r < 4; r++) acc[wm][nt][r] = 0.0f;

    for (int c = 0; c < 2; c++) {
#pragma unroll
        for (int it = 0; it < 4; it++) {
            int f4 = t + it * 256;
            int mt  = f4 >> 7;
            int off = f4 & 127;
            *(uint4*)&As[mt][off * 4] =
                *(const uint4*)&g_goutp16[(mtb + mt) * 1024 + c * 512 + off * 4];
        }
#pragma unroll
        for (int it = 0; it < 4; it++) {
            int f4 = t + it * 256;
            *(uint4*)&Bs[f4 * 4] = *(const uint4*)&wp[c * 4096 + f4 * 4];
        }
        __syncthreads();

#pragma unroll
        for (int ksl = 0; ksl < 4; ksl++) {
            uint4 afr[2];
            afr[0] = *(const uint4*)&As[warp_m * 2 + 0][ksl * 128 + lane * 4];
            afr[1] = *(const uint4*)&As[warp_m * 2 + 1][ksl * 128 + lane * 4];
            uint2 bfr[8];
#pragma unroll
            for (int nt = 0; nt < 8; nt++)
                bfr[nt] = *(const uint2*)&Bs[ksl * 1024 + (warp_n * 8 + nt) * 64 + lane * 2];
#pragma unroll
            for (int wm = 0; wm < 2; wm++)
#pragma unroll
                for (int nt = 0; nt < 8; nt++) {
                    asm volatile(
                        "mma.sync.aligned.m16n8k16.row.col.f32.f16.f16.f32 "
                        "{%0,%1,%2,%3}, {%4,%5,%6,%7}, {%8,%9}, {%0,%1,%2,%3};"
                        : "+f"(acc[wm][nt][0]), "+f"(acc[wm][nt][1]),
                          "+f"(acc[wm][nt][2]), "+f"(acc[wm][nt][3])
                        : "r"(afr[wm].x), "r"(afr[wm].y), "r"(afr[wm].z), "r"(afr[wm].w),
                          "r"(bfr[nt].x), "r"(bfr[nt].y));
                }
        }
        __syncthreads();
    }

    int g   = lane >> 2;
    int tid = lane & 3;
    int m0 = blockIdx.x * 128;
#pragma unroll
    for (int wm = 0; wm < 2; wm++) {
        int row0 = m0 + warp_m * 32 + wm * 16 + g;
#pragma unroll
        for (int nt = 0; nt < 8; nt++) {
            int col = warp_n * 64 + nt * 8 + tid * 2;
            float b0 = bias[col], b1 = bias[col + 1];
            *(float2*)&out[(size_t)row0 * 128 + col] =
                make_float2(acc[wm][nt][0] + b0, acc[wm][nt][1] + b1);
            *(float2*)&out[(size_t)(row0 + 8) * 128 + col] =
                make_float2(acc[wm][nt][2] + b0, acc[wm][nt][3] + b1);
        }
    }
}

// ---------------- launch ----------------------------------------------------
extern "C" void kernel_launch(void* const* d_in, const int* in_sizes, int n_in,
                              void* d_out, int out_size) {
    const float* pair = (const float*)d_in[0];
    const float* ln_w = (const float*)d_in[1];
    const float* ln_b = (const float*)d_in[2];
    const float* Wq   = (const float*)d_in[3];
    const float* Wk   = (const float*)d_in[4];
    const float* Wv   = (const float*)d_in[5];
    const float* Wb   = (const float*)d_in[6];
    const float* Wg   = (const float*)d_in[7];
    const float* bg   = (const float*)d_in[8];
    const float* Wo   = (const float*)d_in[9];
    const float* bo   = (const float*)d_in[10];
    float* out = (float*)d_out;

    cudaFuncSetAttribute(attn_mma_kernel, cudaFuncAttributeMaxDynamicSharedMemorySize,
                         (4096 + 4096 + 8 * 256) * (int)sizeof(unsigned int));

    ln_fused_kernel<<<NROW / 16, 512>>>(pair, ln_w, ln_b, Wb);
    permute_w_kernel<<<5, 256>>>(Wq, Wk, Wv, Wg, Wo);

    proj_gemm_kernel<<<dim3(NROW / 128, 4), 256>>>(bg);

    attn_permute_kernel<<<dim3(L, H), 256>>>();
    attn_mma_kernel<<<dim3(L, 2, H), 256,
                      (4096 + 4096 + 8 * 256) * sizeof(unsigned int)>>>();

    gemm_out_kernel<<<NROW / 128, 256>>>(out, bo);
}